// round 5
// baseline (speedup 1.0000x reference)
#include <cuda_runtime.h>
#include <math.h>

// Problem shapes (fixed by the reference)
#define BATCH      16384
#define N_FEATURES 128
#define HIDDEN     64
#define NUM_TASKS  50000

// Bucketing: task >> 4 -> 3125 bins; duplicates of a task share a bin ->
// adjacent perm slots -> concurrent warps -> L2 dedup of the 32KB W1 tiles.
#define BIN_SHIFT 4
#define NBINS     3125

#define THREADS   64                 // 2 warps per CTA
#define CTAS      4144               // 148 * 28 -> all-resident (launch_bounds(64,28))
#define NWARPS    (CTAS * 2)         // 8288

__device__ int g_hist[NBINS];        // zero at load; re-zeroed in phase C each run
__device__ int g_cursor[NBINS];      // recomputed each run
__device__ int g_perm[BATCH];
__device__ unsigned g_cnt_leaf[64];  // self-resetting barrier counters
__device__ unsigned g_cnt_root;
__device__ volatile unsigned g_rel[3];  // rotating release flags; cycle is replay-invariant

// Two-level grid barrier. Safe because all CTAS are co-resident
// (grid == 148*28, regs capped by __launch_bounds__(64,28)).
// Barrier k sets g_rel[k]=1 and clears g_rel[(k+2)%3]; counters self-reset.
// After a full run the flag state returns to (0,0,1), so every graph replay
// (and the first call, from (0,0,0)) behaves identically.
__device__ __forceinline__ void grid_barrier(int cta, int k) {
    __syncthreads();
    if (threadIdx.x == 0) {
        __threadfence();
        const int leaf = cta & 63;                       // 4144 = 64*64 + 48
        const unsigned leafN = 64u + (leaf < 48 ? 1u : 0u);
        if (atomicAdd(&g_cnt_leaf[leaf], 1u) == leafN - 1u) {
            atomicExch(&g_cnt_leaf[leaf], 0u);
            if (atomicAdd(&g_cnt_root, 1u) == 63u) {
                atomicExch(&g_cnt_root, 0u);
                g_rel[(k + 2) % 3] = 0u;                 // clear previous flag
                __threadfence();
                g_rel[k] = 1u;                           // release
            }
        }
        while (g_rel[k] == 0u) __nanosleep(128);
        __threadfence();
    }
    __syncthreads();
}

// exact GELU: 0.5*x*(1+erf(x/sqrt(2)))
__device__ __forceinline__ float gelu_exact(float v) {
    return 0.5f * v * (1.0f + erff(v * 0.70710678118654752f));
}

__global__ __launch_bounds__(THREADS, 28)
void hypernet_fused(const float* __restrict__ x,
                    const int*   __restrict__ task_ids,
                    const float* __restrict__ l1_emb,   // [NUM_TASKS, 128*64]
                    const float* __restrict__ l1_bias,  // [NUM_TASKS, 64]
                    const float* __restrict__ l2_emb,   // [NUM_TASKS, 64]
                    const float* __restrict__ l2_bias,  // [NUM_TASKS, 1]
                    float*       __restrict__ out)      // [BATCH, 1]
{
    __shared__ float xs[2][N_FEATURES];
    __shared__ int   warp_sums[2];

    const int cta  = blockIdx.x;
    const int tid  = threadIdx.x;
    const int warp = tid >> 5;
    const int lane = tid & 31;

    // ---------- Phase A: histogram (4 samples per CTA) ----------
    if (tid < 4) {
        int s = cta * 4 + tid;
        if (s < BATCH) atomicAdd(&g_hist[task_ids[s] >> BIN_SHIFT], 1);
    }
    grid_barrier(cta, 0);

    // ---------- Phase B: exclusive scan of 3125 bins (CTA 0 only) ----------
    if (cta == 0) {
        const int BPT = 49;                      // 64*49 = 3136 >= 3125
        const int lo = tid * BPT;
        const int hi = min(lo + BPT, NBINS);
        int s = 0;
        for (int b = lo; b < hi; ++b) s += g_hist[b];
        // scan 64 partials: warp shuffle scan + cross-warp combine
        int v = s;
        #pragma unroll
        for (int off = 1; off < 32; off <<= 1) {
            int u = __shfl_up_sync(0xffffffffu, v, off);
            if (lane >= off) v += u;
        }
        if (lane == 31) warp_sums[warp] = v;
        __syncthreads();
        int run = v - s + (warp == 1 ? warp_sums[0] : 0);  // exclusive prefix
        for (int b = lo; b < hi; ++b) {
            int c = g_hist[b];
            g_cursor[b] = run;
            run += c;
        }
    }
    grid_barrier(cta, 1);

    // ---------- Phase C: scatter + reset hist for the next replay ----------
    if (tid < 4) {
        int s = cta * 4 + tid;
        if (s < BATCH) {
            int b = task_ids[s] >> BIN_SHIFT;
            int pos = atomicAdd(&g_cursor[b], 1);
            g_perm[pos] = s;
        }
    }
    if (tid == 0 && cta < NBINS) g_hist[cta] = 0;
    grid_barrier(cta, 2);

    // ---------- Phase D: main compute, 2 slots per warp ----------
    const int wgid = cta * 2 + warp;
    const int tf = lane >> 4;
    const int tc = lane & 15;

    for (int slot = wgid; slot < BATCH; slot += NWARPS) {
        __syncwarp();
        const int sample = g_perm[slot];
        const int task   = task_ids[sample];

        // Stage x (float4, coalesced)
        {
            const float4* xg = reinterpret_cast<const float4*>(x + (size_t)sample * N_FEATURES);
            float4 v = xg[lane];
            reinterpret_cast<float4*>(xs[warp])[lane] = v;
        }
        __syncwarp();

        const float4* w1v = reinterpret_cast<const float4*>(
            l1_emb + (size_t)task * (N_FEATURES * HIDDEN)) + tf * 16 + tc;

        float a0 = 0.f, a1 = 0.f, a2 = 0.f, a3 = 0.f;

        #pragma unroll 16
        for (int i = 0; i < N_FEATURES / 2; ++i) {
            const int f = tf + 2 * i;
            float  xv = xs[warp][f];
            float4 wv = w1v[i * 32];
            a0 = fmaf(xv, wv.x, a0);
            a1 = fmaf(xv, wv.y, a1);
            a2 = fmaf(xv, wv.z, a2);
            a3 = fmaf(xv, wv.w, a3);
        }

        a0 += __shfl_xor_sync(0xffffffffu, a0, 16);
        a1 += __shfl_xor_sync(0xffffffffu, a1, 16);
        a2 += __shfl_xor_sync(0xffffffffu, a2, 16);
        a3 += __shfl_xor_sync(0xffffffffu, a3, 16);

        const float4 b1 = reinterpret_cast<const float4*>(l1_bias + (size_t)task * HIDDEN)[tc];
        const float4 w2 = reinterpret_cast<const float4*>(l2_emb  + (size_t)task * HIDDEN)[tc];

        float h0 = gelu_exact(a0 + b1.x);
        float h1 = gelu_exact(a1 + b1.y);
        float h2 = gelu_exact(a2 + b1.z);
        float h3 = gelu_exact(a3 + b1.w);

        float dot = fmaf(h0, w2.x, fmaf(h1, w2.y, fmaf(h2, w2.z, h3 * w2.w)));

        dot += __shfl_xor_sync(0xffffffffu, dot, 8);
        dot += __shfl_xor_sync(0xffffffffu, dot, 4);
        dot += __shfl_xor_sync(0xffffffffu, dot, 2);
        dot += __shfl_xor_sync(0xffffffffu, dot, 1);

        if (lane == 0) {
            out[sample] = dot + __ldg(l2_bias + task);
        }
    }
}

extern "C" void kernel_launch(void* const* d_in, const int* in_sizes, int n_in,
                              void* d_out, int out_size) {
    const float* x       = (const float*)d_in[0];
    const int*   taskids = (const int*)  d_in[1];
    const float* l1_emb  = (const float*)d_in[2];
    const float* l1_bias = (const float*)d_in[3];
    const float* l2_emb  = (const float*)d_in[4];
    const float* l2_bias = (const float*)d_in[5];
    float* out = (float*)d_out;

    hypernet_fused<<<CTAS, THREADS>>>(x, taskids, l1_emb, l1_bias,
                                      l2_emb, l2_bias, out);
}